// round 11
// baseline (speedup 1.0000x reference)
#include <cuda_runtime.h>
#include <math.h>
#include <stdint.h>

#define FULL 0xFFFFFFFFu

// monotone float->u32 key (only used to feed the u32 redux), branchless
__device__ __forceinline__ unsigned f2key(float f) {
    unsigned b = __float_as_uint(f);
    return b ^ (0x80000000u | (unsigned)((int)b >> 31));
}

// float comparator -> FMNMX on the fma pipe
#define CE(i, j) { float a_ = s[i], b_ = s[j]; s[i] = fmaxf(a_, b_); s[j] = fminf(a_, b_); }

__global__ __launch_bounds__(128)
void topk_route_kernel(const float* __restrict__ logits,
                       const float* __restrict__ bias,
                       float* __restrict__ out, int T)
{
    const int lane = threadIdx.x & 31;
    const int warp = threadIdx.x >> 5;
    const int t = blockIdx.x * 4 + warp;
    if (t >= T) return;

    const unsigned lmlt = (1u << lane) - 1u;   // lanemask_lt

    // lane l owns experts [8l, 8l+8); all 8 are in group l>>2
    const float* lg = logits + (size_t)t * 256 + lane * 8;
    float4 x0 = *(const float4*)lg;
    float4 x1 = *(const float4*)(lg + 4);

    // passthrough logits immediately
    float* lo = out + (size_t)T * 16 + (size_t)t * 256 + lane * 8;
    *(float4*)lo = x0;
    *(float4*)(lo + 4) = x1;

    const float4* bp = (const float4*)(bias + lane * 8);
    float4 b0 = __ldg(bp), b1 = __ldg(bp + 1);

    float xx[8] = {x0.x, x0.y, x0.z, x0.w, x1.x, x1.y, x1.z, x1.w};
    float bb[8] = {b0.x, b0.y, b0.z, b0.w, b1.x, b1.y, b1.z, b1.w};

    // sigmoid (precise: ids must be exact) + bias; stay in FLOAT domain
    float orig[8], s[8];
    #pragma unroll
    for (int i = 0; i < 8; i++) {
        float si = 1.0f / (1.0f + expf(-xx[i]));
        orig[i] = si + bb[i];
        s[i] = orig[i];
    }

    // per-lane descending sort (Batcher odd-even, 19 comparators, FMNMX/fma pipe)
    CE(0,1) CE(2,3) CE(4,5) CE(6,7)
    CE(0,2) CE(1,3) CE(4,6) CE(5,7)
    CE(1,2) CE(5,6)
    CE(0,4) CE(1,5) CE(2,6) CE(3,7)
    CE(2,4) CE(3,5)
    CE(1,2) CE(3,4) CE(5,6)

    // group score = top2 sum (per-lane top2 free from sort: s[0], s[1])
    float m1 = s[0], m2 = s[1];
    #pragma unroll
    for (int off = 1; off <= 2; off <<= 1) {
        float o1 = __shfl_xor_sync(FULL, m1, off);
        float o2 = __shfl_xor_sync(FULL, m2, off);
        float l2 = fminf(m1, o1);
        m1 = fmaxf(m1, o1);
        m2 = fmaxf(l2, fmaxf(m2, o2));
    }
    float gs = m1 + m2;   // identical across each quad

    // group rank via two ballots (8x8 comparison matrix, exact jax ties)
    const int grp = lane >> 2;
    const int f1 = lane & 7;
    const int f2 = f1 ^ 4;
    float gf1 = __shfl_sync(FULL, gs, f1 * 4);
    float gf2 = __shfl_sync(FULL, gs, f2 * 4);
    bool p1 = (gf1 > gs) || (gf1 == gs && f1 < grp);
    bool p2 = (gf2 > gs) || (gf2 == gs && f2 < grp);
    unsigned bq1 = __ballot_sync(FULL, p1);
    unsigned bq2 = __ballot_sync(FULL, p2);
    int rank = __popc((bq1 >> (4 * grp)) & 0xF) + __popc((bq2 >> (4 * grp)) & 0xF);
    bool sel = rank < 4;   // top-4 groups

    // mask unselected groups to 0.0f (reference semantics); FSEL on fp pipe
    #pragma unroll
    for (int i = 0; i < 8; i++) s[i] = sel ? s[i] : 0.0f;

    // 8 extraction rounds; heads converted to u32 keys per round for REDUX.
    // brec init 1: lanes >= 8 resolve to a valid gidx (in-bounds bias gather).
    float krecf = 0.0f; unsigned brec = 1;
    #pragma unroll
    for (int r = 0; r < 8; r++) {
        unsigned key0 = f2key(s[0]);
        unsigned kmax = __reduce_max_sync(FULL, key0);
        bool eq = (key0 == kmax);
        unsigned bal = __ballot_sync(FULL, eq);
        if (lane == r) { krecf = s[0]; brec = bal; }       // s[0] == max as float
        if (r < 7) {
            bool p = eq && ((bal & lmlt) == 0u);           // lowest-lane winner shifts
            #pragma unroll
            for (int i = 0; i < 7 - r; i++) s[i] = p ? s[i + 1] : s[i];
        }
    }
    // fix krecf for the recording lane: it recorded its OWN head; the true max
    // is the winner's head — broadcast via the ballot lane below.
    int wrec = __ffs((int)brec) - 1;

    // krecf currently holds lane r's own head, not the warp max. Re-derive the
    // exact winner value from the winner lane's original list: first match by
    // re-broadcast of the winner's head is not retained, so instead recover via
    // orig[] scan using float equality against the winner's sorted value.
    // Simpler and exact: shfl the winner lane's consumed-count... — we instead
    // recover the value directly: lane k reads the winner's orig list and the
    // winner's head value at round k was the warp max; that value equals the
    // (#wins by wrec before round k + 1)-th largest of wrec's list. To avoid
    // that bookkeeping we recompute: the max at round k is the k-th largest
    // overall, which equals the value we balloted on. Recover it from wrec:
    // all lanes with eq held it in s[0]; the recording lane may differ.
    // -> broadcast the winner's recorded-by-itself value:
    //    at round r, every lane with eq==true had s[0] == max, so ANY such lane
    //    works; wrec is one of them. But we only stored our own head.
    // Use orig-based recovery below with the value from lane wrec's heads:
    // we re-fetch it via a shfl of the per-round winner head values is gone, so
    // instead recover krecf by shfl from a lane that had eq (lane wrec itself
    // recorded nothing). Use: krec_true = (I was in ballot at my round? my head)
    // -> if recording lane had eq, krecf is already the max. If not, take it
    // from the winner via the orig scan: position found by max-match fails.
    //
    // Correctness restoration: take the value from the winner lane explicitly.
    // Each lane k needs the round-k max; lanes that had eq at round k held it.
    // We broadcast from wrec's ORIGINAL sorted list: the round-k winner value is
    // wrec's (m)-th sorted element where m = number of rounds < k won by wrec.
    // m = popcount over previous rounds is not retained either.
    //
    // Fallback that is exact and cheap: scan wrec's orig for the LARGEST value
    // that, among wrec's elements, has not been assigned to an earlier round.
    // Equivalent: m = number of earlier rounds whose winner lane == wrec.
    // Compute via ballot of (wrec values) across lanes (each lane holds its
    // own wrec): match count below.
    unsigned wball = 0;
    #pragma unroll
    for (int j = 0; j < 8; j++) {
        int wj = __shfl_sync(FULL, wrec, j);
        if (j < lane || lane >= 8) { /* count only earlier rounds for my lane */ }
        wball |= (unsigned)(wj == wrec && j < lane) << j;
    }
    int m = (lane < 8) ? __popc(wball) : 0;

    // winner's sorted list: reconstruct by shfl of wrec's orig then local sort?
    // wrec's SORTED values: shfl wrec's post-sort... s[] was destroyed by shifts
    // in lanes, but NOT in non-winning positions... simplest exact path: shfl
    // wrec's orig[8], sort locally (19 comparators), take element m.
    float gk[8];
    #pragma unroll
    for (int i = 0; i < 8; i++) gk[i] = __shfl_sync(FULL, orig[i], wrec);
    // sort gk descending (only lanes 0..7 need it, but all lanes run it)
    {
        float* s2 = gk;
        #define CE2(i, j) { float a_ = s2[i], b_ = s2[j]; s2[i] = fmaxf(a_, b_); s2[j] = fminf(a_, b_); }
        CE2(0,1) CE2(2,3) CE2(4,5) CE2(6,7)
        CE2(0,2) CE2(1,3) CE2(4,6) CE2(5,7)
        CE2(1,2) CE2(5,6)
        CE2(0,4) CE2(1,5) CE2(2,6) CE2(3,7)
        CE2(2,4) CE2(3,5)
        CE2(1,2) CE2(3,4) CE2(5,6)
        #undef CE2
    }
    float kval = gk[0];
    #pragma unroll
    for (int i = 1; i < 8; i++) kval = (i == m) ? gk[i] : kval;   // kval = gk[m]

    // position of kval in wrec's ORIGINAL order (first match = lowest index)
    float go[8];
    #pragma unroll
    for (int i = 0; i < 8; i++) go[i] = __shfl_sync(FULL, orig[i], wrec);
    int pos = 7;
    #pragma unroll
    for (int i = 6; i >= 0; i--) pos = (go[i] == kval) ? i : pos;
    int gidx = (wrec << 3) + pos;

    // weight = unbiased score = biased - bias ; normalize (fast div ok); scale
    float w = kval - __ldg(bias + gidx);
    float sum = w;
    sum += __shfl_xor_sync(FULL, sum, 1);
    sum += __shfl_xor_sync(FULL, sum, 2);
    sum += __shfl_xor_sync(FULL, sum, 4);
    float wn = __fdividef(w, sum) * 2.5f;

    if (lane < 8) {
        out[(size_t)t * 8 + lane] = wn;
        out[(size_t)T * 8 + (size_t)t * 8 + lane] = (float)gidx;
    }
}

extern "C" void kernel_launch(void* const* d_in, const int* in_sizes, int n_in,
                              void* d_out, int out_size)
{
    // inputs: hidden_states (unused), router_logits [T,256], correction_bias [256]
    const float* logits = (const float*)d_in[1];
    const float* bias   = (const float*)d_in[2];
    float* out = (float*)d_out;

    int T = in_sizes[1] / 256;
    int blocks = (T + 3) / 4;              // 1 token per warp, 4 warps per block
    topk_route_kernel<<<blocks, 128>>>(logits, bias, out, T);
}

// round 12
// speedup vs baseline: 1.0171x; 1.0171x over previous
#include <cuda_runtime.h>
#include <math.h>
#include <stdint.h>

#define FULL 0xFFFFFFFFu

// monotone float->u32 key, branchless
__device__ __forceinline__ unsigned f2key(float f) {
    unsigned b = __float_as_uint(f);
    return b ^ (0x80000000u | (unsigned)((int)b >> 31));
}
__device__ __forceinline__ float key2f(unsigned k) {
    unsigned b = (k & 0x80000000u) ? (k ^ 0x80000000u) : ~k;
    return __uint_as_float(b);
}

// u32 comparator, descending (hi keeps max)
#define CEC(i, j) { unsigned a_ = c[i], b_ = c[j]; c[i] = umax(a_, b_); c[j] = umin(a_, b_); }

__global__ __launch_bounds__(128)
void topk_route_kernel(const float* __restrict__ logits,
                       const float* __restrict__ bias,
                       float* __restrict__ out, int T)
{
    const int lane = threadIdx.x & 31;
    const int warp = threadIdx.x >> 5;
    const int tb = (blockIdx.x * 4 + warp) * 2;   // 2 tokens per warp
    if (tb >= T) return;

    const int sub = lane >> 4;          // 0 = token A (lanes 0-15), 1 = token B
    const int sl  = lane & 15;          // lane within subgroup
    const int t   = tb + sub;           // my token
    const bool tv = (t < T);
    const int tt  = tv ? t : (T - 1);   // clamped for loads
    const unsigned hm = sub ? 0xFFFF0000u : 0x0000FFFFu;   // subgroup mask
    const unsigned slmask = (1u << sl) - 1u;               // sub-lanemask_lt

    // lane owns experts [16*sl, 16*sl+16) of its token; group = sl>>1
    const float* lg = logits + (size_t)tt * 256 + sl * 16;
    float4 x0 = *(const float4*)lg;
    float4 x1 = *(const float4*)(lg + 4);
    float4 x2 = *(const float4*)(lg + 8);
    float4 x3 = *(const float4*)(lg + 12);

    // passthrough logits immediately
    if (tv) {
        float* lo = out + (size_t)T * 16 + (size_t)t * 256 + sl * 16;
        *(float4*)lo       = x0;
        *(float4*)(lo + 4) = x1;
        *(float4*)(lo + 8) = x2;
        *(float4*)(lo + 12)= x3;
    }

    const float4* bp = (const float4*)(bias + sl * 16);
    float4 b0 = __ldg(bp), b1 = __ldg(bp + 1), b2 = __ldg(bp + 2), b3 = __ldg(bp + 3);

    float xx[16] = {x0.x,x0.y,x0.z,x0.w, x1.x,x1.y,x1.z,x1.w,
                    x2.x,x2.y,x2.z,x2.w, x3.x,x3.y,x3.z,x3.w};
    float bb[16] = {b0.x,b0.y,b0.z,b0.w, b1.x,b1.y,b1.z,b1.w,
                    b2.x,b2.y,b2.z,b2.w, b3.x,b3.y,b3.z,b3.w};

    // sigmoid (precise: ids must be exact) + bias -> monotone keys
    unsigned orig[16], c[16];
    #pragma unroll
    for (int i = 0; i < 16; i++) {
        float si = 1.0f / (1.0f + expf(-xx[i]));
        orig[i] = f2key(si + bb[i]);
        c[i] = orig[i];
    }

    // ---- per-lane top-8-of-16 (values only; positions recovered later) ----
    // sort c[0..7] desc (Batcher odd-even, 19 comparators)
    CEC(0,1) CEC(2,3) CEC(4,5) CEC(6,7)
    CEC(0,2) CEC(1,3) CEC(4,6) CEC(5,7)
    CEC(1,2) CEC(5,6)
    CEC(0,4) CEC(1,5) CEC(2,6) CEC(3,7)
    CEC(2,4) CEC(3,5)
    CEC(1,2) CEC(3,4) CEC(5,6)
    // sort c[8..15] desc
    CEC(8,9) CEC(10,11) CEC(12,13) CEC(14,15)
    CEC(8,10) CEC(9,11) CEC(12,14) CEC(13,15)
    CEC(9,10) CEC(13,14)
    CEC(8,12) CEC(9,13) CEC(10,14) CEC(11,15)
    CEC(10,12) CEC(11,13)
    CEC(9,10) CEC(11,12) CEC(13,14)
    // bitonic half-cleaner: top-8 of the 16 lands in c[0..7] (bitonic order)
    CEC(0,15) CEC(1,14) CEC(2,13) CEC(3,12) CEC(4,11) CEC(5,10) CEC(6,9) CEC(7,8)
    // bitonic sort-8 desc on c[0..7]
    CEC(0,4) CEC(1,5) CEC(2,6) CEC(3,7)
    CEC(0,2) CEC(1,3) CEC(4,6) CEC(5,7)
    CEC(0,1) CEC(2,3) CEC(4,5) CEC(6,7)

    unsigned s[8];
    #pragma unroll
    for (int i = 0; i < 8; i++) s[i] = c[i];

    // ---- group score = top2 sum; merge with partner lane (xor 1, same group)
    unsigned m1 = s[0], m2 = s[1];
    {
        unsigned o1 = __shfl_xor_sync(FULL, m1, 1);
        unsigned o2 = __shfl_xor_sync(FULL, m2, 1);
        unsigned l2 = umin(m1, o1);
        m1 = umax(m1, o1);
        m2 = umax(l2, umax(m2, o2));
    }
    float gs = key2f(m1) + key2f(m2);   // identical across the 2 lanes of a group

    // ---- rank own group among the 8 (exact jax tie semantics)
    const int grp = sl >> 1;
    const int base = lane & 16;          // subgroup base lane
    int rank = 0;
    #pragma unroll
    for (int j = 0; j < 8; j++) {
        float gj = __shfl_sync(FULL, gs, base + 2 * j);
        rank += ((gj > gs) || (gj == gs && j < grp)) ? 1 : 0;
    }
    bool sel = rank < 4;   // top-4 groups

    // mask unselected groups to key(0.0f)
    #pragma unroll
    for (int i = 0; i < 8; i++) s[i] = sel ? s[i] : 0x80000000u;

    // ---- 8 extraction rounds over the subgroup (serves both tokens at once)
    // brec init 1: non-recording lanes resolve to a valid gidx (in-bounds gather)
    unsigned krec = 0x80000000u, brec = 1;
    #pragma unroll
    for (int r = 0; r < 8; r++) {
        unsigned kmax = __reduce_max_sync(hm, s[0]);
        bool eq = (s[0] == kmax);
        unsigned bal = __ballot_sync(FULL, eq);
        unsigned half = (bal >> (base)) & 0xFFFFu;   // my subgroup's eq bits
        if (sl == r) { krec = kmax; brec = half; }
        if (r < 7) {
            bool p = eq && ((half & slmask) == 0u);  // lowest-sublane winner shifts
            #pragma unroll
            for (int i = 0; i < 7 - r; i++) s[i] = p ? s[i + 1] : s[i];
        }
    }
    int wrec = __ffs((int)brec) - 1;                 // winner sublane (0..15)

    // ---- index recovery: scan winner lane's orig[16] for first match
    int src = base + wrec;
    int pos = 15;
    #pragma unroll
    for (int i = 15; i >= 0; i--) {
        unsigned gk = __shfl_sync(FULL, orig[i], src);
        pos = (gk == krec) ? i : pos;                // final: first (lowest) match
    }
    int gidx = (wrec << 4) + pos;

    // ---- weight = unbiased score = biased - bias; normalize over octet; scale
    float w = key2f(krec) - __ldg(bias + gidx);
    float sum = w;
    sum += __shfl_xor_sync(FULL, sum, 1);
    sum += __shfl_xor_sync(FULL, sum, 2);
    sum += __shfl_xor_sync(FULL, sum, 4);
    float wn = __fdividef(w, sum) * 2.5f;

    if (sl < 8 && tv) {
        out[(size_t)t * 8 + sl] = wn;
        out[(size_t)T * 8 + (size_t)t * 8 + sl] = (float)gidx;
    }
}

extern "C" void kernel_launch(void* const* d_in, const int* in_sizes, int n_in,
                              void* d_out, int out_size)
{
    // inputs: hidden_states (unused), router_logits [T,256], correction_bias [256]
    const float* logits = (const float*)d_in[1];
    const float* bias   = (const float*)d_in[2];
    float* out = (float*)d_out;

    int T = in_sizes[1] / 256;
    int warps = (T + 1) / 2;               // 2 tokens per warp
    int blocks = (warps + 3) / 4;          // 4 warps per block
    topk_route_kernel<<<blocks, 128>>>(logits, bias, out, T);
}

// round 13
// speedup vs baseline: 1.1380x; 1.1189x over previous
#include <cuda_runtime.h>
#include <math.h>
#include <stdint.h>

#define FULL 0xFFFFFFFFu

// monotone float->u32 key, branchless
__device__ __forceinline__ unsigned f2key(float f) {
    unsigned b = __float_as_uint(f);
    return b ^ (0x80000000u | (unsigned)((int)b >> 31));
}
__device__ __forceinline__ float key2f(unsigned k) {
    unsigned b = (k & 0x80000000u) ? (k ^ 0x80000000u) : ~k;
    return __uint_as_float(b);
}

#define CE(i, j) { unsigned a_ = s[i], b_ = s[j]; s[i] = umax(a_, b_); s[j] = umin(a_, b_); }

__global__ __launch_bounds__(256)
void topk_route_kernel(const float* __restrict__ logits,
                       const float* __restrict__ bias,
                       float* __restrict__ out, int T)
{
    const int lane = threadIdx.x & 31;
    const int warp = threadIdx.x >> 5;
    const int t = blockIdx.x * 8 + warp;
    if (t >= T) return;

    const unsigned lmlt = (1u << lane) - 1u;   // lanemask_lt

    // lane l owns experts [8l, 8l+8); all 8 are in group l>>2
    const float4* lg = (const float4*)(logits + (size_t)t * 256 + lane * 8);
    float4 x0 = __ldcs(lg);        // streaming: no reuse
    float4 x1 = __ldcs(lg + 1);

    // passthrough logits immediately (streaming stores: no reuse)
    float4* lo = (float4*)(out + (size_t)T * 16 + (size_t)t * 256 + lane * 8);
    __stcs(lo, x0);
    __stcs(lo + 1, x1);

    const float4* bp = (const float4*)(bias + lane * 8);
    float4 b0 = __ldg(bp), b1 = __ldg(bp + 1);

    float xx[8] = {x0.x, x0.y, x0.z, x0.w, x1.x, x1.y, x1.z, x1.w};
    float bb[8] = {b0.x, b0.y, b0.z, b0.w, b1.x, b1.y, b1.z, b1.w};

    // sigmoid (precise expf + IEEE div: score bits must match reference
    // exactly — selection ordering is bit-sensitive) + bias -> monotone keys
    unsigned orig[8], s[8];
    #pragma unroll
    for (int i = 0; i < 8; i++) {
        float si = 1.0f / (1.0f + expf(-xx[i]));
        orig[i] = f2key(si + bb[i]);
        s[i] = orig[i];
    }

    // per-lane descending sort (Batcher odd-even, 19 comparators)
    CE(0,1) CE(2,3) CE(4,5) CE(6,7)
    CE(0,2) CE(1,3) CE(4,6) CE(5,7)
    CE(1,2) CE(5,6)
    CE(0,4) CE(1,5) CE(2,6) CE(3,7)
    CE(2,4) CE(3,5)
    CE(1,2) CE(3,4) CE(5,6)

    // group score = top2 sum (per-lane top2 free from sort: s[0], s[1])
    unsigned m1 = s[0], m2 = s[1];
    #pragma unroll
    for (int off = 1; off <= 2; off <<= 1) {
        unsigned o1 = __shfl_xor_sync(FULL, m1, off);
        unsigned o2 = __shfl_xor_sync(FULL, m2, off);
        unsigned l2 = umin(m1, o1);
        m1 = umax(m1, o1);
        m2 = umax(l2, umax(m2, o2));
    }
    float gs = key2f(m1) + key2f(m2);   // identical across each quad

    // group rank via two ballots (8x8 comparison matrix, exact jax ties)
    const int grp = lane >> 2;
    const int f1 = lane & 7;
    const int f2 = f1 ^ 4;
    float gf1 = __shfl_sync(FULL, gs, f1 * 4);
    float gf2 = __shfl_sync(FULL, gs, f2 * 4);
    bool p1 = (gf1 > gs) || (gf1 == gs && f1 < grp);
    bool p2 = (gf2 > gs) || (gf2 == gs && f2 < grp);
    unsigned bq1 = __ballot_sync(FULL, p1);
    unsigned bq2 = __ballot_sync(FULL, p2);
    int rank = __popc((bq1 >> (4 * grp)) & 0xF) + __popc((bq2 >> (4 * grp)) & 0xF);
    bool sel = rank < 4;   // top-4 groups

    // mask unselected groups to key(0.0f)
    #pragma unroll
    for (int i = 0; i < 8; i++) s[i] = sel ? s[i] : 0x80000000u;

    // 8 extraction rounds; triangular shift (round r needs depth <= 7-r after).
    // brec init 1: lanes >= 8 resolve to a valid gidx (in-bounds bias gather).
    unsigned krec = 0, brec = 1;
    #pragma unroll
    for (int r = 0; r < 8; r++) {
        unsigned kmax = __reduce_max_sync(FULL, s[0]);
        bool eq = (s[0] == kmax);
        unsigned bal = __ballot_sync(FULL, eq);
        if (lane == r) { krec = kmax; brec = bal; }
        if (r < 7) {
            bool p = eq && ((bal & lmlt) == 0u);   // lowest-lane winner shifts
            #pragma unroll
            for (int i = 0; i < 7 - r; i++) s[i] = p ? s[i + 1] : s[i];
        }
    }
    int wrec = __ffs((int)brec) - 1;

    // index recovery: bitmask of matches in lane wrec's orig[], first = lowest
    unsigned mmask = 0;
    #pragma unroll
    for (int i = 0; i < 8; i++) {
        unsigned gk = __shfl_sync(FULL, orig[i], wrec);
        mmask |= (unsigned)(gk == krec) << i;
    }
    int pos = __ffs((int)(mmask | 0x80u)) - 1;   // guard keeps pos in [0,7]
    int gidx = (wrec << 3) + pos;

    // weight = unbiased score = biased - bias ; normalize (fast div ok); scale
    float w = key2f(krec) - __ldg(bias + gidx);
    float sum = w;
    sum += __shfl_xor_sync(FULL, sum, 1);
    sum += __shfl_xor_sync(FULL, sum, 2);
    sum += __shfl_xor_sync(FULL, sum, 4);
    float wn = __fdividef(w, sum) * 2.5f;

    if (lane < 8) {
        out[(size_t)t * 8 + lane] = wn;
        out[(size_t)T * 8 + (size_t)t * 8 + lane] = (float)gidx;
    }
}

extern "C" void kernel_launch(void* const* d_in, const int* in_sizes, int n_in,
                              void* d_out, int out_size)
{
    // inputs: hidden_states (unused), router_logits [T,256], correction_bias [256]
    const float* logits = (const float*)d_in[1];
    const float* bias   = (const float*)d_in[2];
    float* out = (float*)d_out;

    int T = in_sizes[1] / 256;
    int blocks = (T + 7) / 8;              // 1 token per warp, 8 warps per block
    topk_route_kernel<<<blocks, 256>>>(logits, bias, out, T);
}

// round 14
// speedup vs baseline: 1.1577x; 1.0173x over previous
#include <cuda_runtime.h>
#include <math.h>
#include <stdint.h>

#define FULL 0xFFFFFFFFu

// monotone float->u32 key, branchless
__device__ __forceinline__ unsigned f2key(float f) {
    unsigned b = __float_as_uint(f);
    return b ^ (0x80000000u | (unsigned)((int)b >> 31));
}
__device__ __forceinline__ float key2f(unsigned k) {
    unsigned b = (k & 0x80000000u) ? (k ^ 0x80000000u) : ~k;
    return __uint_as_float(b);
}

#define CE(i, j) { unsigned a_ = s[i], b_ = s[j]; s[i] = umax(a_, b_); s[j] = umin(a_, b_); }

__global__ __launch_bounds__(128)
void topk_route_kernel(const float* __restrict__ logits,
                       const float* __restrict__ bias,
                       float* __restrict__ out, int T)
{
    const int lane = threadIdx.x & 31;
    const int warp = threadIdx.x >> 5;
    const int t = blockIdx.x * 4 + warp;
    if (t >= T) return;

    const unsigned lmlt = (1u << lane) - 1u;   // lanemask_lt

    // lane l owns experts [8l, 8l+8); all 8 are in group l>>2
    const float* lg = logits + (size_t)t * 256 + lane * 8;
    float4 x0 = *(const float4*)lg;
    float4 x1 = *(const float4*)(lg + 4);

    // passthrough logits immediately
    float* lo = out + (size_t)T * 16 + (size_t)t * 256 + lane * 8;
    *(float4*)lo = x0;
    *(float4*)(lo + 4) = x1;

    const float4* bp = (const float4*)(bias + lane * 8);
    float4 b0 = __ldg(bp), b1 = __ldg(bp + 1);

    float xx[8] = {x0.x, x0.y, x0.z, x0.w, x1.x, x1.y, x1.z, x1.w};
    float bb[8] = {b0.x, b0.y, b0.z, b0.w, b1.x, b1.y, b1.z, b1.w};

    // sigmoid (precise expf + IEEE div: selection ordering is bit-sensitive;
    // cheaper variants risk id flips worth ~2e-3 rel_err each) -> monotone keys
    unsigned orig[8], s[8];
    #pragma unroll
    for (int i = 0; i < 8; i++) {
        float si = 1.0f / (1.0f + expf(-xx[i]));
        orig[i] = f2key(si + bb[i]);
        s[i] = orig[i];
    }

    // per-lane descending sort (Batcher odd-even, 19 comparators)
    CE(0,1) CE(2,3) CE(4,5) CE(6,7)
    CE(0,2) CE(1,3) CE(4,6) CE(5,7)
    CE(1,2) CE(5,6)
    CE(0,4) CE(1,5) CE(2,6) CE(3,7)
    CE(2,4) CE(3,5)
    CE(1,2) CE(3,4) CE(5,6)

    // group score = top2 sum (per-lane top2 free from sort: s[0], s[1])
    unsigned m1 = s[0], m2 = s[1];
    #pragma unroll
    for (int off = 1; off <= 2; off <<= 1) {
        unsigned o1 = __shfl_xor_sync(FULL, m1, off);
        unsigned o2 = __shfl_xor_sync(FULL, m2, off);
        unsigned l2 = umin(m1, o1);
        m1 = umax(m1, o1);
        m2 = umax(l2, umax(m2, o2));
    }
    float gs = key2f(m1) + key2f(m2);   // identical across each quad

    // group rank via two ballots (8x8 comparison matrix, exact jax ties)
    const int grp = lane >> 2;
    const int f1 = lane & 7;
    const int f2 = f1 ^ 4;
    float gf1 = __shfl_sync(FULL, gs, f1 * 4);
    float gf2 = __shfl_sync(FULL, gs, f2 * 4);
    bool p1 = (gf1 > gs) || (gf1 == gs && f1 < grp);
    bool p2 = (gf2 > gs) || (gf2 == gs && f2 < grp);
    unsigned bq1 = __ballot_sync(FULL, p1);
    unsigned bq2 = __ballot_sync(FULL, p2);
    int rank = __popc((bq1 >> (4 * grp)) & 0xF) + __popc((bq2 >> (4 * grp)) & 0xF);
    bool sel = rank < 4;   // top-4 groups

    // mask unselected groups to key(0.0f)
    #pragma unroll
    for (int i = 0; i < 8; i++) s[i] = sel ? s[i] : 0x80000000u;

    // 8 extraction rounds; triangular shift (round r needs depth <= 7-r after).
    // brec init 1: lanes >= 8 resolve to a valid gidx (in-bounds bias gather).
    unsigned krec = 0, brec = 1;
    #pragma unroll
    for (int r = 0; r < 8; r++) {
        unsigned kmax = __reduce_max_sync(FULL, s[0]);
        bool eq = (s[0] == kmax);
        unsigned bal = __ballot_sync(FULL, eq);
        if (lane == r) { krec = kmax; brec = bal; }
        if (r < 7) {
            bool p = eq && ((bal & lmlt) == 0u);   // lowest-lane winner shifts
            #pragma unroll
            for (int i = 0; i < 7 - r; i++) s[i] = p ? s[i + 1] : s[i];
        }
    }
    int wrec = __ffs((int)brec) - 1;

    // index recovery: bitmask of matches in lane wrec's orig[], first = lowest
    unsigned mmask = 0;
    #pragma unroll
    for (int i = 0; i < 8; i++) {
        unsigned gk = __shfl_sync(FULL, orig[i], wrec);
        mmask |= (unsigned)(gk == krec) << i;
    }
    int pos = __ffs((int)(mmask | 0x80u)) - 1;   // guard keeps pos in [0,7]
    int gidx = (wrec << 3) + pos;

    // weight = unbiased score = biased - bias ; normalize (fast div ok); scale
    float w = key2f(krec) - __ldg(bias + gidx);
    float sum = w;
    sum += __shfl_xor_sync(FULL, sum, 1);
    sum += __shfl_xor_sync(FULL, sum, 2);
    sum += __shfl_xor_sync(FULL, sum, 4);
    float wn = __fdividef(w, sum) * 2.5f;

    if (lane < 8) {
        out[(size_t)t * 8 + lane] = wn;
        out[(size_t)T * 8 + (size_t)t * 8 + lane] = (float)gidx;
    }
}

extern "C" void kernel_launch(void* const* d_in, const int* in_sizes, int n_in,
                              void* d_out, int out_size)
{
    // inputs: hidden_states (unused), router_logits [T,256], correction_bias [256]
    const float* logits = (const float*)d_in[1];
    const float* bias   = (const float*)d_in[2];
    float* out = (float*)d_out;

    int T = in_sizes[1] / 256;
    int blocks = (T + 3) / 4;              // 1 token per warp, 4 warps per block
    topk_route_kernel<<<blocks, 128>>>(logits, bias, out, T);
}